// round 1
// baseline (speedup 1.0000x reference)
#include <cuda_runtime.h>
#include <cuda_bf16.h>
#include <math.h>

// Problem constants
#define NN    4096      // nodes
#define FIN   512       // input dim
#define HH    4         // heads
#define FF    64        // per-head out dim
#define HF    256       // H*F

// Scratch (device globals: no allocations allowed)
__device__ float g_XW[NN * HF];       // X @ W        [N, H*F]
__device__ float g_f1[HH * NN];       // src scores   [H, N]
__device__ float g_f2[HH * NN];       // dst scores   [H, N]
__device__ float g_M[HH];             // per-head safe max bound

// ---------------------------------------------------------------------------
// Kernel 1: XW = X @ W   (4096x512 @ 512x256), fp32 tiled GEMM
// ---------------------------------------------------------------------------
__global__ void __launch_bounds__(256) gemm_xw(const float* __restrict__ X,
                                               const float* __restrict__ W) {
    __shared__ float Xs[64][16];
    __shared__ float Ws[16][64];

    const int tid = threadIdx.x;
    const int bm = blockIdx.x * 64;
    const int bn = blockIdx.y * 64;
    const int tx = tid & 15;   // col group (4 cols)
    const int ty = tid >> 4;   // row group (4 rows)

    float acc[4][4];
#pragma unroll
    for (int r = 0; r < 4; r++)
#pragma unroll
        for (int c = 0; c < 4; c++) acc[r][c] = 0.f;

    for (int k0 = 0; k0 < FIN; k0 += 16) {
        {
            int r = tid >> 2, c = (tid & 3) * 4;
            *(float4*)&Xs[r][c] = *(const float4*)&X[(bm + r) * FIN + k0 + c];
            int wr = tid >> 4, wc = (tid & 15) * 4;
            *(float4*)&Ws[wr][wc] = *(const float4*)&W[(k0 + wr) * HF + bn + wc];
        }
        __syncthreads();
#pragma unroll
        for (int k = 0; k < 16; k++) {
            float xr[4];
#pragma unroll
            for (int r = 0; r < 4; r++) xr[r] = Xs[ty * 4 + r][k];
            float4 wv = *(const float4*)&Ws[k][tx * 4];
#pragma unroll
            for (int r = 0; r < 4; r++) {
                acc[r][0] += xr[r] * wv.x;
                acc[r][1] += xr[r] * wv.y;
                acc[r][2] += xr[r] * wv.z;
                acc[r][3] += xr[r] * wv.w;
            }
        }
        __syncthreads();
    }
#pragma unroll
    for (int r = 0; r < 4; r++) {
        float4 v = make_float4(acc[r][0], acc[r][1], acc[r][2], acc[r][3]);
        *(float4*)&g_XW[(size_t)(bm + ty * 4 + r) * HF + bn + tx * 4] = v;
    }
}

// ---------------------------------------------------------------------------
// Kernel 2: f1[h,n] = <XW[n,h,:], a_src[h,:]>,  f2 likewise with a_dst
// ---------------------------------------------------------------------------
__global__ void __launch_bounds__(256) f1f2_kernel(const float* __restrict__ a_src,
                                                   const float* __restrict__ a_dst) {
    __shared__ float as_s[HF];
    __shared__ float ad_s[HF];
    const int tid = threadIdx.x;
    as_s[tid] = a_src[tid];
    ad_s[tid] = a_dst[tid];
    __syncthreads();

    const int n = blockIdx.x * 256 + tid;
    const float4* xr = (const float4*)(g_XW + (size_t)n * HF);
    float s1[HH], s2[HH];
#pragma unroll
    for (int h = 0; h < HH; h++) { s1[h] = 0.f; s2[h] = 0.f; }
#pragma unroll
    for (int h = 0; h < HH; h++) {
#pragma unroll
        for (int f4 = 0; f4 < 16; f4++) {
            float4 x = xr[h * 16 + f4];
            float4 a1 = *(const float4*)&as_s[h * 64 + f4 * 4];
            float4 a2 = *(const float4*)&ad_s[h * 64 + f4 * 4];
            s1[h] += x.x * a1.x + x.y * a1.y + x.z * a1.z + x.w * a1.w;
            s2[h] += x.x * a2.x + x.y * a2.y + x.z * a2.z + x.w * a2.w;
        }
    }
#pragma unroll
    for (int h = 0; h < HH; h++) {
        g_f1[h * NN + n] = s1[h];
        g_f2[h * NN + n] = s2[h];
    }
}

// ---------------------------------------------------------------------------
// Kernel 3: per-head safe max bound M[h] = lrelu(max_i f1[h,i] + max_j f2[h,j])
// ---------------------------------------------------------------------------
__global__ void __launch_bounds__(256) max_kernel() {
    const int tid = threadIdx.x;
    const int lane = tid & 31;
    const int w = tid >> 5;                 // 0..7 : warps 0-3 -> f1, 4-7 -> f2
    const float* src = (w < 4) ? (g_f1 + w * NN) : (g_f2 + (w - 4) * NN);
    float m = -3.4e38f;
    for (int n = lane; n < NN; n += 32) m = fmaxf(m, src[n]);
#pragma unroll
    for (int o = 16; o; o >>= 1) m = fmaxf(m, __shfl_xor_sync(0xFFFFFFFFu, m, o));
    __shared__ float ms[8];
    if (lane == 0) ms[w] = m;
    __syncthreads();
    if (tid < HH) {
        float s = ms[tid] + ms[tid + 4];
        g_M[tid] = s > 0.f ? s : 0.2f * s;
    }
}

// ---------------------------------------------------------------------------
// Kernel 4: fused masked-softmax attention + aggregation + ELU
//   grid = 128 blocks (32-row i-tiles), 256 threads
//   smem: xw tile [32][256], w tile [4][32][33] (padded), f1 cache, l cache
// ---------------------------------------------------------------------------
#define TI 32
#define TJ 32
// smem layout (floats)
#define OFF_XW   0                      // 32*256 = 8192
#define OFF_W    8192                   // 4*32*33 = 4224
#define OFF_F1   (8192 + 4224)          // 128
#define OFF_L    (8192 + 4224 + 128)    // 128
#define SMEM_FLOATS (8192 + 4224 + 128 + 128)
#define SMEM_BYTES  (SMEM_FLOATS * 4)

__global__ void __launch_bounds__(256) gat_attn(const int* __restrict__ A,
                                                float* __restrict__ out) {
    extern __shared__ float smem[];
    float* xw_s = smem + OFF_XW;
    float* w_s  = smem + OFF_W;   // [h][i][j] stride 33 on j
    float* f1_s = smem + OFF_F1;  // [h][i]
    float* l_s  = smem + OFF_L;   // [h][i]

    const int tid = threadIdx.x;
    const int i0 = blockIdx.x * TI;

    // Shared decomposition (same for FMA and writer roles):
    const int row  = tid & 31;   // FMA: output row (lane dim) / writer: j column
    const int cg   = tid >> 5;   // FMA: 32-col group / writer: (head, i-half) set
    const int head = cg >> 1;
    const int ibase = (cg & 1) * 16;   // writer handles rows ibase..ibase+15

    // Cache f1 for this i-tile
    if (tid < HH * TI)
        f1_s[tid] = g_f1[(tid >> 5) * NN + i0 + (tid & 31)];
    __syncthreads();

    const float Mreg = g_M[head];

    float acc[32];
#pragma unroll
    for (int c = 0; c < 32; c++) acc[c] = 0.f;
    float lsum = 0.f;

    for (int j0 = 0; j0 < NN; j0 += TJ) {
        // ---- Phase A: global loads + weight computation into REGISTERS ----
        // (overlaps previous tile's FMA loop; no smem writes yet)
        float4 xv[8];
        {
            const float4* xwg = (const float4*)(g_XW + (size_t)j0 * HF);
#pragma unroll
            for (int v = 0; v < 8; v++) xv[v] = xwg[v * 256 + tid];
        }
        float wout[16];
        {
            const float f2v = g_f2[head * NN + j0 + row];   // row == writer j
#pragma unroll
            for (int k = 0; k < 16; k++) {
                const int i = ibase + k;
                const int a = A[(size_t)(i0 + i) * NN + j0 + row];
                float s = f1_s[head * 32 + i] + f2v;
                s = s > 0.f ? s : 0.2f * s;
                wout[k] = a ? __expf(s - Mreg) : 0.f;
            }
        }

        __syncthreads();   // previous tile's FMA done -> safe to overwrite smem

        // ---- Phase B: commit to smem ----
        {
            float* dst = xw_s;
#pragma unroll
            for (int v = 0; v < 8; v++)
                *(float4*)(dst + (v * 256 + tid) * 4) = xv[v];
#pragma unroll
            for (int k = 0; k < 16; k++)
                w_s[head * (32 * 33) + (ibase + k) * 33 + row] = wout[k];
        }
        __syncthreads();

        // ---- Phase C: FMA loop ----
        // thread -> out row (i0+row), cols [cg*32, cg*32+32); xw reads broadcast
#pragma unroll 4
        for (int j = 0; j < TJ; j++) {
            const float w = w_s[head * (32 * 33) + row * 33 + j];
            lsum += w;
            const float4* xr = (const float4*)(xw_s + j * HF + cg * 32);
#pragma unroll
            for (int v = 0; v < 8; v++) {
                float4 x = xr[v];
                acc[v * 4 + 0] += w * x.x;
                acc[v * 4 + 1] += w * x.y;
                acc[v * 4 + 2] += w * x.z;
                acc[v * 4 + 3] += w * x.w;
            }
        }
    }

    // ---- Epilogue: normalize + ELU + store ----
    __syncthreads();
    if ((cg & 1) == 0) l_s[head * 32 + row] = lsum;
    __syncthreads();
    const float inv = 1.f / l_s[head * 32 + row];

    float* op = out + (size_t)(i0 + row) * HF + cg * 32;
#pragma unroll
    for (int v = 0; v < 8; v++) {
        float4 r;
        float v0 = acc[v * 4 + 0] * inv;
        float v1 = acc[v * 4 + 1] * inv;
        float v2 = acc[v * 4 + 2] * inv;
        float v3 = acc[v * 4 + 3] * inv;
        r.x = v0 > 0.f ? v0 : expm1f(v0);
        r.y = v1 > 0.f ? v1 : expm1f(v1);
        r.z = v2 > 0.f ? v2 : expm1f(v2);
        r.w = v3 > 0.f ? v3 : expm1f(v3);
        *(float4*)(op + v * 4) = r;
    }
}

// ---------------------------------------------------------------------------
extern "C" void kernel_launch(void* const* d_in, const int* in_sizes, int n_in,
                              void* d_out, int out_size) {
    const float* X     = (const float*)d_in[0];
    const int*   A     = (const int*)d_in[1];
    const float* W     = (const float*)d_in[2];
    const float* a_src = (const float*)d_in[3];
    const float* a_dst = (const float*)d_in[4];
    float* out = (float*)d_out;

    gemm_xw<<<dim3(NN / 64, HF / 64), 256>>>(X, W);
    f1f2_kernel<<<NN / 256, 256>>>(a_src, a_dst);
    max_kernel<<<1, 256>>>();

    cudaFuncSetAttribute(gat_attn, cudaFuncAttributeMaxDynamicSharedMemorySize,
                         SMEM_BYTES);
    gat_attn<<<NN / TI, 256, SMEM_BYTES>>>(A, out);
}